// round 16
// baseline (speedup 1.0000x reference)
#include <cuda_runtime.h>
#include <cuda_bf16.h>
#include <math.h>

typedef unsigned int u32;
typedef __nv_bfloat16 bf;

#define B_  4
#define S_  1024
#define D_  1024
#define E_  4
#define H_  2816
#define BS_ (B_*S_)
#define CAP BS_
#define ADA6 (6*D_)
#define BSD ((long)BS_*D_)
#define K2D 2048
#define K2H (2*H_)
#define STG1 49152
#define SMEM1 (4*STG1)
#define SMEM2 (4*STG1)

// ---------------- device scratch ----------------
__device__ __align__(16) float g_ada [B_*ADA6];
__device__ __align__(16) bf    g_hs  [(long)BS_*K2D];
__device__ __align__(16) bf    g_wqkvT[(long)3*D_*K2D];
__device__ __align__(16) bf    g_woT [(long)D_*K2D];
__device__ __align__(16) float g_q   [BS_*D_];
__device__ __align__(16) float g_k   [BS_*D_];
__device__ __align__(16) float g_mu  [2*BS_];
__device__ __align__(16) float g_rs  [2*BS_];
__device__ __align__(16) bf    g_qT  [(long)B_*D_*K2D];
__device__ __align__(16) bf    g_kT  [(long)B_*D_*K2D];
__device__ __align__(16) bf    g_vs  [(long)BS_*K2D];
__device__ __align__(16) float g_sc  [(long)B_*D_*D_];
__device__ __align__(16) bf    g_at  [(long)B_*D_*K2D];
__device__ __align__(16) bf    g_aos [(long)BS_*K2D];
__device__ __align__(16) float g_x1  [BS_*D_];
__device__ __align__(16) bf    g_h2s [(long)BS_*K2D];
__device__ __align__(16) bf    g_w1T [(long)E_*H_*K2D];
__device__ __align__(16) bf    g_w3T [(long)E_*H_*K2D];
__device__ __align__(16) bf    g_w2T [(long)E_*D_*K2H];
__device__ __align__(16) bf    g_gs  [(long)E_*CAP*K2H];
__device__ __align__(16) float g_ebuf[(long)E_*CAP*D_];
__device__ __align__(16) float g_lg  [BS_*E_];
__device__ __align__(16) float g_pr  [BS_*E_];
__device__ int   g_cnt [E_];
__device__ int   g_list[E_*CAP];
__device__ int   g_te  [BS_*2];
__device__ int   g_tp  [BS_*2];
__device__ __align__(16) float g_tw  [BS_*2];

// ---------------- helpers ----------------
__device__ __forceinline__ u32 smem_u32(const void* p) {
    u32 a;
    asm("{ .reg .u64 t; cvta.to.shared.u64 t, %1; cvt.u32.u64 %0, t; }" : "=r"(a) : "l"(p));
    return a;
}
__device__ __forceinline__ u32 swz(u32 o) { return o ^ ((o >> 3) & 0x70); }
__device__ __forceinline__ void bsplit(float v, bf& h, bf& l) {
    h = __float2bfloat16(v);
    l = __float2bfloat16(v - __bfloat162float(h));
}
__device__ __forceinline__ u32 pk2(bf a, bf b) {
    return (u32)__bfloat16_as_ushort(a) | ((u32)__bfloat16_as_ushort(b) << 16);
}
#define CP16(dst, src) asm volatile("cp.async.cg.shared.global [%0], [%1], 16;" :: "r"(dst), "l"(src))
#define CP_COMMIT()    asm volatile("cp.async.commit_group;")
#define CP_WAIT2()     asm volatile("cp.async.wait_group 2;")
#define LDM4(r, ad) asm volatile("ldmatrix.sync.aligned.m8n8.x4.shared.b16 {%0,%1,%2,%3}, [%4];" \
    : "=r"((r)[0]), "=r"((r)[1]), "=r"((r)[2]), "=r"((r)[3]) : "r"(ad))
#define MMA(c, a, b0, b1) asm volatile( \
    "mma.sync.aligned.m16n8k16.row.col.f32.bf16.bf16.f32 " \
    "{%0,%1,%2,%3}, {%4,%5,%6,%7}, {%8,%9}, {%0,%1,%2,%3};" \
    : "+f"((c)[0]), "+f"((c)[1]), "+f"((c)[2]), "+f"((c)[3]) \
    : "r"((a)[0]), "r"((a)[1]), "r"((a)[2]), "r"((a)[3]), "r"(b0), "r"(b1))

// ============ bf16 split GEMM: C[M,N] = A[M,2K](3seg) * B[N,2K](3seg)^T ============
template<int EPI, bool GATHER>
__global__ void __launch_bounds__(256, 1) hgemm(
    const bf* __restrict__ A, long aZ,
    const bf* __restrict__ Bm, long bZ,
    int Kr, int N, int Mcap,
    const int* __restrict__ counts, const int* __restrict__ list,
    float* __restrict__ Cf, float* __restrict__ Ck, long cZ,
    bf* __restrict__ Cs, int outW, long csZ,
    const float* __restrict__ aux,
    const float* __restrict__ gate, int gateStride)
{
    extern __shared__ __align__(16) char smem[];
    const int z = blockIdx.z;
    const int Meff = counts ? counts[z] : Mcap;
    const int m0 = blockIdx.x * 256;
    if (m0 >= Meff) return;
    const int n0 = blockIdx.y * 128;
    const int tid = threadIdx.x, wid = tid >> 5, lane = tid & 31;
    const int wm = wid >> 1, wn = wid & 1;
    const u32 sb = smem_u32(smem);
    const long K2 = 2L * Kr;

    const bf* Az = A + (long)z * aZ;
    const bf* Bz = Bm + (long)z * bZ;

    long aRow[8];
    int  jA = tid & 7;
#pragma unroll
    for (int i = 0; i < 8; i++) {
        int r = (i * 256 + tid) >> 3;
        int gm = m0 + r; if (gm > Meff - 1) gm = Meff - 1;
        aRow[i] = GATHER ? (long)list[(long)z * CAP + gm] : (long)gm;
    }
    u32 dA[8], dB[4];
#pragma unroll
    for (int i = 0; i < 8; i++) { int r = (i * 256 + tid) >> 3; dA[i] = swz((u32)(r * 128 + jA * 16)); }
#pragma unroll
    for (int i = 0; i < 4; i++) { int r = (i * 256 + tid) >> 3; dB[i] = swz((u32)(r * 128 + jA * 16)); }

    float acc[4][8][4];
#pragma unroll
    for (int a = 0; a < 4; a++)
#pragma unroll
        for (int b = 0; b < 8; b++)
#pragma unroll
            for (int c = 0; c < 4; c++) acc[a][b][c] = 0.f;

    const int seglen = Kr >> 6;
    const int NC = 3 * seglen;

    auto issue = [&](int c) {
        int seg = c / seglen;
        int kin = (c - seg * seglen) << 6;
        int aOff = (seg == 2 ? Kr : 0) + kin + jA * 8;
        int bOff = (seg == 1 ? Kr : 0) + kin + jA * 8;
        u32 base = sb + (u32)(c & 3) * STG1;
#pragma unroll
        for (int i = 0; i < 8; i++)
            CP16(base + dA[i], Az + aRow[i] * K2 + aOff);
#pragma unroll
        for (int i = 0; i < 4; i++) {
            int r = (i * 256 + tid) >> 3;
            CP16(base + 32768 + dB[i], Bz + (long)(n0 + r) * K2 + bOff);
        }
    };

    issue(0); CP_COMMIT();
    issue(1); CP_COMMIT();
    issue(2); CP_COMMIT();

    for (int c = 0; c < NC; c++) {
        CP_WAIT2();
        __syncthreads();
        if (c + 3 < NC) issue(c + 3);
        CP_COMMIT();
        u32 aB = sb + (u32)(c & 3) * STG1, bB = aB + 32768;
#pragma unroll
        for (int s = 0; s < 4; s++) {
            u32 afr[4][4], bfr[4][4];
#pragma unroll
            for (int mi = 0; mi < 4; mi++) {
                int row = wm * 64 + mi * 16 + (lane & 7) + ((lane >> 3) & 1) * 8;
                int kb = s * 32 + (lane >> 4) * 16;
                LDM4(afr[mi], aB + swz((u32)(row * 128 + kb)));
            }
#pragma unroll
            for (int ni = 0; ni < 4; ni++) {
                int nrow = wn * 64 + ni * 16 + (lane & 7) + (lane >> 4) * 8;
                int kb = s * 32 + ((lane >> 3) & 1) * 16;
                LDM4(bfr[ni], bB + swz((u32)(nrow * 128 + kb)));
            }
#pragma unroll
            for (int mi = 0; mi < 4; mi++)
#pragma unroll
                for (int nj = 0; nj < 8; nj++)
                    MMA(acc[mi][nj], afr[mi], bfr[nj >> 1][(nj & 1) * 2], bfr[nj >> 1][(nj & 1) * 2 + 1]);
        }
    }

#pragma unroll
    for (int mi = 0; mi < 4; mi++) {
#pragma unroll
        for (int half = 0; half < 2; half++) {
            int row = m0 + wm * 64 + mi * 16 + (lane >> 2) + half * 8;
            if (row >= Meff) continue;
#pragma unroll
            for (int nj = 0; nj < 8; nj++) {
                int col = n0 + wn * 64 + nj * 8 + (lane & 3) * 2;
                float v0 = acc[mi][nj][half * 2], v1 = acc[mi][nj][half * 2 + 1];
                if (EPI == 0) {
                    *(float2*)(Cf + (long)z * cZ + (long)row * N + col) = make_float2(v0, v1);
                } else if (EPI == 1) {
                    int bb = row >> 10;
                    const float2 rs = *(const float2*)(aux + (long)row * N + col);
                    const float* gv = gate + (long)bb * gateStride + col;
                    *(float2*)(Cf + (long)row * N + col) = make_float2(rs.x + gv[0] * v0, rs.y + gv[1] * v1);
                } else if (EPI == 4) {
                    if (col < 1024) {
                        *(float2*)(Cf + (long)row * 1024 + col) = make_float2(v0, v1);
                    } else if (col < 2048) {
                        *(float2*)(Ck + (long)row * 1024 + (col - 1024)) = make_float2(v0, v1);
                    } else {
                        int cc = col - 2048;
                        bf h0, l0, h1, l1;
                        bsplit(v0, h0, l0); bsplit(v1, h1, l1);
                        bf* o = Cs + (long)row * 2048 + cc;
                        *(u32*)(o) = pk2(h0, h1);
                        *(u32*)(o + 1024) = pk2(l0, l1);
                    }
                } else {
                    bf h0, l0, h1, l1;
                    bsplit(v0, h0, l0); bsplit(v1, h1, l1);
                    bf* o = Cs + (long)z * csZ + (long)row * 2 * outW + col;
                    *(u32*)(o) = pk2(h0, h1);
                    *(u32*)(o + outW) = pk2(l0, l1);
                }
            }
        }
    }
}

// ============ dual-B GEMM (MoE up, fused): gs = split(sin(A*B1^T) * (A*B2^T)) ============
__global__ void __launch_bounds__(256, 1) hgemm2(
    const bf* __restrict__ A,
    const bf* __restrict__ B1m, const bf* __restrict__ B2m, long bZ,
    int Kr, int N, int Mcap,
    const int* __restrict__ counts, const int* __restrict__ list,
    bf* __restrict__ Cs, long csZ)
{
    extern __shared__ __align__(16) char smem[];
    const int z = blockIdx.z;
    const int Meff = counts[z];
    const int m0 = blockIdx.x * 128;
    if (m0 >= Meff) return;
    const int n0 = blockIdx.y * 128;
    const int tid = threadIdx.x, wid = tid >> 5, lane = tid & 31;
    const int wm = wid >> 2, wn = wid & 3;
    const u32 sb = smem_u32(smem);
    const long K2 = 2L * Kr;

    const bf* B1z = B1m + (long)z * bZ;
    const bf* B2z = B2m + (long)z * bZ;

    long aRow[4];
    int jA = tid & 7;
#pragma unroll
    for (int i = 0; i < 4; i++) {
        int r = (i * 256 + tid) >> 3;
        int gm = m0 + r; if (gm > Meff - 1) gm = Meff - 1;
        aRow[i] = (long)list[(long)z * CAP + gm];
    }
    u32 dT[4];
#pragma unroll
    for (int i = 0; i < 4; i++) { int r = (i * 256 + tid) >> 3; dT[i] = swz((u32)(r * 128 + jA * 16)); }

    float acc1[4][4][4], acc2[4][4][4];
#pragma unroll
    for (int a = 0; a < 4; a++)
#pragma unroll
        for (int b = 0; b < 4; b++)
#pragma unroll
            for (int c = 0; c < 4; c++) { acc1[a][b][c] = 0.f; acc2[a][b][c] = 0.f; }

    const int seglen = Kr >> 6;
    const int NC = 3 * seglen;

    auto issue = [&](int c) {
        int seg = c / seglen;
        int kin = (c - seg * seglen) << 6;
        int aOff = (seg == 2 ? Kr : 0) + kin + jA * 8;
        int bOff = (seg == 1 ? Kr : 0) + kin + jA * 8;
        u32 base = sb + (u32)(c & 3) * STG1;
#pragma unroll
        for (int i = 0; i < 4; i++) {
            int r = (i * 256 + tid) >> 3;
            CP16(base + dT[i], A + aRow[i] * K2 + aOff);
            CP16(base + 16384 + dT[i], B1z + (long)(n0 + r) * K2 + bOff);
            CP16(base + 32768 + dT[i], B2z + (long)(n0 + r) * K2 + bOff);
        }
    };

    issue(0); CP_COMMIT();
    issue(1); CP_COMMIT();
    issue(2); CP_COMMIT();

    for (int c = 0; c < NC; c++) {
        CP_WAIT2();
        __syncthreads();
        if (c + 3 < NC) issue(c + 3);
        CP_COMMIT();
        u32 aB = sb + (u32)(c & 3) * STG1, b1B = aB + 16384, b2B = aB + 32768;
#pragma unroll
        for (int s = 0; s < 4; s++) {
            u32 afr[4][4], bfr1[2][4], bfr2[2][4];
#pragma unroll
            for (int mi = 0; mi < 4; mi++) {
                int row = wm * 64 + mi * 16 + (lane & 7) + ((lane >> 3) & 1) * 8;
                int kb = s * 32 + (lane >> 4) * 16;
                LDM4(afr[mi], aB + swz((u32)(row * 128 + kb)));
            }
#pragma unroll
            for (int bi = 0; bi < 2; bi++) {
                int nrow = wn * 32 + bi * 16 + (lane & 7) + (lane >> 4) * 8;
                int kb = s * 32 + ((lane >> 3) & 1) * 16;
                LDM4(bfr1[bi], b1B + swz((u32)(nrow * 128 + kb)));
                LDM4(bfr2[bi], b2B + swz((u32)(nrow * 128 + kb)));
            }
#pragma unroll
            for (int mi = 0; mi < 4; mi++)
#pragma unroll
                for (int nj = 0; nj < 4; nj++) {
                    MMA(acc1[mi][nj], afr[mi], bfr1[nj >> 1][(nj & 1) * 2], bfr1[nj >> 1][(nj & 1) * 2 + 1]);
                    MMA(acc2[mi][nj], afr[mi], bfr2[nj >> 1][(nj & 1) * 2], bfr2[nj >> 1][(nj & 1) * 2 + 1]);
                }
        }
    }

#pragma unroll
    for (int mi = 0; mi < 4; mi++) {
#pragma unroll
        for (int half = 0; half < 2; half++) {
            int row = m0 + wm * 64 + mi * 16 + (lane >> 2) + half * 8;
            if (row >= Meff) continue;
#pragma unroll
            for (int nj = 0; nj < 4; nj++) {
                int col = n0 + wn * 32 + nj * 8 + (lane & 3) * 2;
                float v0 = sinf(acc1[mi][nj][half * 2]) * acc2[mi][nj][half * 2];
                float v1 = sinf(acc1[mi][nj][half * 2 + 1]) * acc2[mi][nj][half * 2 + 1];
                bf h0, l0, h1, l1;
                bsplit(v0, h0, l0); bsplit(v1, h1, l1);
                bf* o = Cs + (long)z * csZ + (long)row * (long)(2 * N) + col;
                *(u32*)(o) = pk2(h0, h1);
                *(u32*)(o + N) = pk2(l0, l1);
            }
        }
    }
}

// ---------------- prep kernels ----------------
__global__ void __launch_bounds__(256) transS(const float* __restrict__ in, bf* __restrict__ out,
                                              int R, int C, long inZ, long outZ)
{
    __shared__ float t[64][65];
    int z = blockIdx.z;
    const float* iz = in + (long)z * inZ;
    bf* oz = out + (long)z * outZ;
    int c0 = blockIdx.x * 64, r0 = blockIdx.y * 64;
    int tid = threadIdx.x;
    int lc = (tid & 15) * 4, lr = tid >> 4;
#pragma unroll
    for (int p = 0; p < 4; p++) {
        int r = lr + p * 16;
        float4 v = *(const float4*)&iz[(long)(r0 + r) * C + c0 + lc];
        t[r][lc] = v.x; t[r][lc + 1] = v.y; t[r][lc + 2] = v.z; t[r][lc + 3] = v.w;
    }
    __syncthreads();
    int wr = (tid & 15) * 4, wc = tid >> 4;
#pragma unroll
    for (int p = 0; p < 4; p++) {
        int c = wc + p * 16;
        float v0 = t[wr + 0][c], v1 = t[wr + 1][c], v2 = t[wr + 2][c], v3 = t[wr + 3][c];
        bf h0, l0, h1, l1, h2, l2, h3, l3;
        bsplit(v0, h0, l0); bsplit(v1, h1, l1); bsplit(v2, h2, l2); bsplit(v3, h3, l3);
        long base = (long)(c0 + c) * 2 * R + r0 + wr;
        uint2 hh, ll;
        hh.x = pk2(h0, h1); hh.y = pk2(h2, h3);
        ll.x = pk2(l0, l1); ll.y = pk2(l2, l3);
        *(uint2*)&oz[base] = hh;
        *(uint2*)&oz[base + R] = ll;
    }
}

__global__ void __launch_bounds__(256) transQKV(const float* __restrict__ wq,
    const float* __restrict__ wk, const float* __restrict__ wv, bf* __restrict__ out)
{
    __shared__ float t[64][65];
    int which = blockIdx.z;
    const float* iz = which == 0 ? wq : (which == 1 ? wk : wv);
    bf* oz = out + (long)which * D_ * K2D;
    int c0 = blockIdx.x * 64, r0 = blockIdx.y * 64;
    int tid = threadIdx.x;
    int lc = (tid & 15) * 4, lr = tid >> 4;
#pragma unroll
    for (int p = 0; p < 4; p++) {
        int r = lr + p * 16;
        float4 v = *(const float4*)&iz[(long)(r0 + r) * D_ + c0 + lc];
        t[r][lc] = v.x; t[r][lc + 1] = v.y; t[r][lc + 2] = v.z; t[r][lc + 3] = v.w;
    }
    __syncthreads();
    int wr = (tid & 15) * 4, wc = tid >> 4;
#pragma unroll
    for (int p = 0; p < 4; p++) {
        int c = wc + p * 16;
        float v0 = t[wr + 0][c], v1 = t[wr + 1][c], v2 = t[wr + 2][c], v3 = t[wr + 3][c];
        bf h0, l0, h1, l1, h2, l2, h3, l3;
        bsplit(v0, h0, l0); bsplit(v1, h1, l1); bsplit(v2, h2, l2); bsplit(v3, h3, l3);
        long base = (long)(c0 + c) * 2 * D_ + r0 + wr;
        uint2 hh, ll;
        hh.x = pk2(h0, h1); hh.y = pk2(h2, h3);
        ll.x = pk2(l0, l1); ll.y = pk2(l2, l3);
        *(uint2*)&oz[base] = hh;
        *(uint2*)&oz[base + D_] = ll;
    }
}

// per-row mean/rstd for q_/k_; also zeroes cnt (block 0)
__global__ void __launch_bounds__(256) qk_stats(const float* __restrict__ q,
    const float* __restrict__ k, float* __restrict__ mu, float* __restrict__ rs,
    int* __restrict__ cnt, float eps)
{
    if (blockIdx.x == 0 && threadIdx.x < E_) cnt[threadIdx.x] = 0;
    int row = blockIdx.x * 8 + (threadIdx.x >> 5);
    int lane = threadIdx.x & 31;
    const float* src = (row < BS_) ? (q + (long)row * D_) : (k + (long)(row - BS_) * D_);
    float s1 = 0.f, s2 = 0.f;
#pragma unroll
    for (int j = 0; j < 8; j++) {
        float4 v = *(const float4*)&src[j * 128 + lane * 4];
        s1 += v.x + v.y + v.z + v.w;
        s2 += v.x * v.x + v.y * v.y + v.z * v.z + v.w * v.w;
    }
#pragma unroll
    for (int o = 16; o; o >>= 1) {
        s1 += __shfl_xor_sync(0xffffffffu, s1, o);
        s2 += __shfl_xor_sync(0xffffffffu, s2, o);
    }
    if (lane == 0) {
        float mean = s1 * (1.f / D_);
        float var = s2 * (1.f / D_) - mean * mean;
        mu[row] = mean;
        rs[row] = rsqrtf(var + eps);
    }
}

// fused normalize + transpose + split for q and k
__global__ void __launch_bounds__(256) transSN(const float* __restrict__ qin,
    const float* __restrict__ kin, bf* __restrict__ qout, bf* __restrict__ kout,
    const float* __restrict__ qw, const float* __restrict__ qb,
    const float* __restrict__ kw, const float* __restrict__ kb,
    const float* __restrict__ mu, const float* __restrict__ rs)
{
    __shared__ float t[64][65];
    int z = blockIdx.z;
    int isK = z >= B_;
    int b = z & 3;
    const float* iz = (isK ? kin : qin) + (long)b * S_ * D_;
    bf* oz = (isK ? kout : qout) + (long)b * D_ * K2D;
    const float* w = isK ? kw : qw;
    const float* bb = isK ? kb : qb;
    int statOff = (isK ? BS_ : 0) + b * S_;
    int c0 = blockIdx.x * 64, r0 = blockIdx.y * 64;
    int tid = threadIdx.x;
    int lc = (tid & 15) * 4, lr = tid >> 4;
    float4 wv = *(const float4*)&w[c0 + lc];
    float4 bv = *(const float4*)&bb[c0 + lc];
#pragma unroll
    for (int p = 0; p < 4; p++) {
        int r = lr + p * 16;
        float m = mu[statOff + r0 + r];
        float rv = rs[statOff + r0 + r];
        float4 v = *(const float4*)&iz[(long)(r0 + r) * D_ + c0 + lc];
        t[r][lc]     = (v.x - m) * rv * wv.x + bv.x;
        t[r][lc + 1] = (v.y - m) * rv * wv.y + bv.y;
        t[r][lc + 2] = (v.z - m) * rv * wv.z + bv.z;
        t[r][lc + 3] = (v.w - m) * rv * wv.w + bv.w;
    }
    __syncthreads();
    int wr = (tid & 15) * 4, wc = tid >> 4;
#pragma unroll
    for (int p = 0; p < 4; p++) {
        int c = wc + p * 16;
        float v0 = t[wr + 0][c], v1 = t[wr + 1][c], v2 = t[wr + 2][c], v3 = t[wr + 3][c];
        bf h0, l0, h1, l1, h2, l2, h3, l3;
        bsplit(v0, h0, l0); bsplit(v1, h1, l1); bsplit(v2, h2, l2); bsplit(v3, h3, l3);
        long base = (long)(c0 + c) * K2D + r0 + wr;
        uint2 hh, ll;
        hh.x = pk2(h0, h1); hh.y = pk2(h2, h3);
        ll.x = pk2(l0, l1); ll.y = pk2(l2, l3);
        *(uint2*)&oz[base] = hh;
        *(uint2*)&oz[base + S_] = ll;
    }
}

__global__ void __launch_bounds__(128) ada_kernel(const float* __restrict__ adaln,
    const float* __restrict__ W, const float* __restrict__ bias, float* __restrict__ ada)
{
    __shared__ float s[B_ * D_];
    int col = blockIdx.x * 128 + threadIdx.x;
    for (int i = threadIdx.x; i < B_ * D_; i += 128) {
        float v = adaln[i];
        s[i] = v / (1.f + expf(-v));
    }
    __syncthreads();
    float a0 = 0.f, a1 = 0.f, a2 = 0.f, a3 = 0.f;
    for (int k = 0; k < D_; k++) {
        float w = W[(long)k * ADA6 + col];
        a0 = fmaf(s[k], w, a0); a1 = fmaf(s[D_ + k], w, a1);
        a2 = fmaf(s[2 * D_ + k], w, a2); a3 = fmaf(s[3 * D_ + k], w, a3);
    }
    float bv = bias[col];
    ada[col] = a0 + bv; ada[ADA6 + col] = a1 + bv;
    ada[2L * ADA6 + col] = a2 + bv; ada[3L * ADA6 + col] = a3 + bv;
}

// LN width 1024: warp-per-row; optional fp32 out, split out, and fused router logits
__global__ void __launch_bounds__(256) ln_kernel(const float* __restrict__ in,
    float* __restrict__ outF, bf* __restrict__ outS,
    const float* __restrict__ w, const float* __restrict__ b,
    const float* __restrict__ scale, const float* __restrict__ shift,
    int adaStride, float eps,
    const float* __restrict__ rw, const float* __restrict__ rb, float* __restrict__ lg)
{
    int row = blockIdx.x * 8 + (threadIdx.x >> 5);
    int lane = threadIdx.x & 31;
    const float* xr = in + (long)row * D_;
    float4 v[8];
    float s1 = 0.f, s2 = 0.f;
#pragma unroll
    for (int j = 0; j < 8; j++) {
        v[j] = *(const float4*)&xr[j * 128 + lane * 4];
        s1 += v[j].x + v[j].y + v[j].z + v[j].w;
        s2 += v[j].x * v[j].x + v[j].y * v[j].y + v[j].z * v[j].z + v[j].w * v[j].w;
    }
#pragma unroll
    for (int o = 16; o; o >>= 1) {
        s1 += __shfl_xor_sync(0xffffffffu, s1, o);
        s2 += __shfl_xor_sync(0xffffffffu, s2, o);
    }
    float mean = s1 * (1.f / D_);
    float var = s2 * (1.f / D_) - mean * mean;
    float rsv = rsqrtf(var + eps);
    int bb = row >> 10;
#pragma unroll
    for (int j = 0; j < 8; j++) {
        int c0 = j * 128 + lane * 4;
        float4 wv = *(const float4*)&w[c0];
        float4 bv = *(const float4*)&b[c0];
        float o0 = (v[j].x - mean) * rsv * wv.x + bv.x;
        float o1 = (v[j].y - mean) * rsv * wv.y + bv.y;
        float o2 = (v[j].z - mean) * rsv * wv.z + bv.z;
        float o3 = (v[j].w - mean) * rsv * wv.w + bv.w;
        if (scale) {
            float4 sv = *(const float4*)&scale[(long)bb * adaStride + c0];
            float4 hv = *(const float4*)&shift[(long)bb * adaStride + c0];
            o0 = o0 * (1.f + sv.x) + hv.x;
            o1 = o1 * (1.f + sv.y) + hv.y;
            o2 = o2 * (1.f + sv.z) + hv.z;
            o3 = o3 * (1.f + sv.w) + hv.w;
        }
        v[j] = make_float4(o0, o1, o2, o3);
        if (outF)
            *(float4*)&outF[(long)row * D_ + c0] = v[j];
        if (outS) {
            bf h0, l0, h1, l1, h2, l2, h3, l3;
            bsplit(o0, h0, l0); bsplit(o1, h1, l1);
            bsplit(o2, h2, l2); bsplit(o3, h3, l3);
            bf* os = outS + (long)row * K2D;
            uint2 hh, ll;
            hh.x = pk2(h0, h1); hh.y = pk2(h2, h3);
            ll.x = pk2(l0, l1); ll.y = pk2(l2, l3);
            *(uint2*)&os[c0] = hh;
            *(uint2*)&os[D_ + c0] = ll;
        }
    }
    if (rw) {
        float a0 = 0.f, a1 = 0.f, a2 = 0.f, a3 = 0.f;
#pragma unroll
        for (int j = 0; j < 8; j++) {
            float hvv[4] = { v[j].x, v[j].y, v[j].z, v[j].w };
#pragma unroll
            for (int u = 0; u < 4; u++) {
                int k = j * 128 + lane * 4 + u;
                float4 wv = *(const float4*)&rw[(long)k * 4];
                a0 = fmaf(hvv[u], wv.x, a0); a1 = fmaf(hvv[u], wv.y, a1);
                a2 = fmaf(hvv[u], wv.z, a2); a3 = fmaf(hvv[u], wv.w, a3);
            }
        }
#pragma unroll
        for (int o = 16; o; o >>= 1) {
            a0 += __shfl_xor_sync(0xffffffffu, a0, o);
            a1 += __shfl_xor_sync(0xffffffffu, a1, o);
            a2 += __shfl_xor_sync(0xffffffffu, a2, o);
            a3 += __shfl_xor_sync(0xffffffffu, a3, o);
        }
        if (lane == 0) {
            lg[(long)row * 4 + 0] = a0 + rb[0];
            lg[(long)row * 4 + 1] = a1 + rb[1];
            lg[(long)row * 4 + 2] = a2 + rb[2];
            lg[(long)row * 4 + 3] = a3 + rb[3];
        }
    }
}

__global__ void __launch_bounds__(256) softmax_kernel(const float* __restrict__ p, bf* __restrict__ outS) {
    int row = blockIdx.x * 8 + (threadIdx.x >> 5);
    int lane = threadIdx.x & 31;
    const float* r = p + (long)row * D_;
    float4 v[8];
    float m = -1e30f;
#pragma unroll
    for (int j = 0; j < 8; j++) {
        v[j] = *(const float4*)&r[j * 128 + lane * 4];
        m = fmaxf(m, fmaxf(fmaxf(v[j].x, v[j].y), fmaxf(v[j].z, v[j].w)));
    }
#pragma unroll
    for (int o = 16; o; o >>= 1) m = fmaxf(m, __shfl_xor_sync(0xffffffffu, m, o));
    float s = 0.f;
#pragma unroll
    for (int j = 0; j < 8; j++) {
        v[j].x = expf(v[j].x - m); v[j].y = expf(v[j].y - m);
        v[j].z = expf(v[j].z - m); v[j].w = expf(v[j].w - m);
        s += v[j].x + v[j].y + v[j].z + v[j].w;
    }
#pragma unroll
    for (int o = 16; o; o >>= 1) s += __shfl_xor_sync(0xffffffffu, s, o);
    float inv = 1.f / s;
    bf* os = outS + (long)row * K2D;
#pragma unroll
    for (int j = 0; j < 8; j++) {
        int c0 = j * 128 + lane * 4;
        bf h0, l0, h1, l1, h2, l2, h3, l3;
        bsplit(v[j].x * inv, h0, l0); bsplit(v[j].y * inv, h1, l1);
        bsplit(v[j].z * inv, h2, l2); bsplit(v[j].w * inv, h3, l3);
        uint2 hh, ll;
        hh.x = pk2(h0, h1); hh.y = pk2(h2, h3);
        ll.x = pk2(l0, l1); ll.y = pk2(l2, l3);
        *(uint2*)&os[c0] = hh;
        *(uint2*)&os[D_ + c0] = ll;
    }
}

__global__ void __launch_bounds__(256) seqnorm_kernel(float* __restrict__ lg) {
    int b = blockIdx.x >> 2, e = blockIdx.x & 3;
    int t = threadIdx.x;
    float s = 0.f;
    for (int i = t; i < S_; i += 256) {
        float v = lg[((long)(b * S_ + i)) * 4 + e];
        s += v * v;
    }
    __shared__ float sm[8];
#pragma unroll
    for (int o = 16; o; o >>= 1) s += __shfl_down_sync(0xffffffffu, s, o);
    if ((t & 31) == 0) sm[t >> 5] = s;
    __syncthreads();
    if (t == 0) {
        float a = 0.f;
        for (int i = 0; i < 8; i++) a += sm[i];
        sm[0] = 1.f / fmaxf(sqrtf(a), 1e-12f);
    }
    __syncthreads();
    float sc = sm[0];
    for (int i = t; i < S_; i += 256) lg[((long)(b * S_ + i)) * 4 + e] *= sc;
}

__global__ void topk_kernel(const float* __restrict__ lg, float* __restrict__ pr,
    int* __restrict__ cnt, int* __restrict__ list,
    int* __restrict__ te, int* __restrict__ tp, float* __restrict__ tw)
{
    int tok = blockIdx.x * 256 + threadIdx.x;
    if (tok >= BS_) return;
    float l[4];
#pragma unroll
    for (int e = 0; e < 4; e++) l[e] = lg[(long)tok * 4 + e];
    float m = fmaxf(fmaxf(l[0], l[1]), fmaxf(l[2], l[3]));
    float p[4]; float s = 0.f;
#pragma unroll
    for (int e = 0; e < 4; e++) { p[e] = expf(l[e] - m); s += p[e]; }
    float inv = 1.f / s;
#pragma unroll
    for (int e = 0; e < 4; e++) { p[e] *= inv; pr[(long)tok * 4 + e] = p[e]; }
    int a0 = 0;
#pragma unroll
    for (int e = 1; e < 4; e++) if (p[e] > p[a0]) a0 = e;
    int a1 = -1; float pb = -1.f;
#pragma unroll
    for (int e = 0; e < 4; e++) if (e != a0 && p[e] > pb) { pb = p[e]; a1 = e; }
    int s0 = atomicAdd(&cnt[a0], 1); list[a0 * CAP + s0] = tok;
    int s1 = atomicAdd(&cnt[a1], 1); list[a1 * CAP + s1] = tok;
    te[2 * tok] = a0;     tp[2 * tok] = s0;     tw[2 * tok] = p[a0];
    te[2 * tok + 1] = a1; tp[2 * tok + 1] = s1; tw[2 * tok + 1] = p[a1];
}

// vectorized combine: 4 elems/thread
__global__ void combine_kernel(const float* __restrict__ ebuf,
    const int* __restrict__ te, const int* __restrict__ tp,
    const float* __restrict__ tw, float* __restrict__ out)
{
    long gid = ((long)blockIdx.x * 256 + threadIdx.x) * 4;
    int tok = (int)(gid >> 10);
    int d = (int)(gid & 1023);
    int e0 = te[2 * tok], e1 = te[2 * tok + 1];
    float w0 = tw[2 * tok], w1 = tw[2 * tok + 1];
    const float4 a = *(const float4*)&ebuf[((long)e0 * CAP + tp[2 * tok]) * D_ + d];
    const float4 b = *(const float4*)&ebuf[((long)e1 * CAP + tp[2 * tok + 1]) * D_ + d];
    float4 o;
    o.x = w0 * a.x + w1 * b.x;
    o.y = w0 * a.y + w1 * b.y;
    o.z = w0 * a.z + w1 * b.z;
    o.w = w0 * a.w + w1 * b.w;
    *(float4*)&out[gid] = o;
}

__global__ void __launch_bounds__(256) aux_kernel(const float* __restrict__ pr,
                                                  float* __restrict__ out, long out_size)
{
    int t = threadIdx.x;
    float acc = 0.f;
    for (int i = t; i < S_ * E_; i += 256) {
        int s = i >> 2, e = i & 3;
        float av = 0.f;
#pragma unroll
        for (int b = 0; b < B_; b++) av += pr[((long)(b * S_ + s)) * 4 + e];
        av *= 0.25f;
        float d = 0.25f - av;
        acc += d * d;
    }
    __shared__ float sm[8];
#pragma unroll
    for (int o = 16; o; o >>= 1) acc += __shfl_xor_sync(0xffffffffu, acc, o);
    if ((t & 31) == 0) sm[t >> 5] = acc;
    __syncthreads();
    if (t == 0) {
        float a = 0.f;
        for (int i = 0; i < 8; i++) a += sm[i];
        for (long i = BSD; i < out_size; i++) out[i] = a;
    }
}

// ---------------- host launcher ----------------
extern "C" void kernel_launch(void* const* d_in, const int* in_sizes, int n_in,
                              void* d_out, int out_size)
{
    (void)in_sizes; (void)n_in;
    const float* x     = (const float*)d_in[0];
    const float* adaln = (const float*)d_in[2];
    const float* wq    = (const float*)d_in[3];
    const float* wk    = (const float*)d_in[4];
    const float* wv    = (const float*)d_in[5];
    const float* wo    = (const float*)d_in[6];
    const float* qnw   = (const float*)d_in[7];
    const float* qnb   = (const float*)d_in[8];
    const float* knw   = (const float*)d_in[9];
    const float* knb   = (const float*)d_in[10];
    const float* anw   = (const float*)d_in[11];
    const float* anb   = (const float*)d_in[12];
    const float* fnw   = (const float*)d_in[13];
    const float* fnb   = (const float*)d_in[14];
    const float* w1    = (const float*)d_in[15];
    const float* w2    = (const float*)d_in[16];
    const float* w3    = (const float*)d_in[17];
    const float* rw    = (const float*)d_in[18];
    const float* rb    = (const float*)d_in[19];
    const float* adaw  = (const float*)d_in[20];
    const float* adab  = (const float*)d_in[21];
    float* out = (float*)d_out;

    float *ada_, *q_, *k_, *mu_, *rs_, *sc_, *x1_, *lg_, *pr_, *ebuf_, *tw_;
    bf *hs_, *wqkvT_, *woT_, *qT_, *kT_, *vs_, *at_, *aos_, *h2s_, *w1T_, *w3T_, *w2T_, *gs_;
    int *cnt_, *list_, *te_, *tp_;
    cudaGetSymbolAddress((void**)&ada_,  g_ada);
    cudaGetSymbolAddress((void**)&hs_,   g_hs);
    cudaGetSymbolAddress((void**)&wqkvT_,g_wqkvT);
    cudaGetSymbolAddress((void**)&woT_,  g_woT);
    cudaGetSymbolAddress((void**)&q_,    g_q);
    cudaGetSymbolAddress((void**)&k_,    g_k);
    cudaGetSymbolAddress((void**)&mu_,   g_mu);
    cudaGetSymbolAddress((void**)&rs_,   g_rs);
    cudaGetSymbolAddress((void**)&qT_,   g_qT);
    cudaGetSymbolAddress((void**)&kT_,   g_kT);
    cudaGetSymbolAddress((void**)&vs_,   g_vs);
    cudaGetSymbolAddress((void**)&sc_,   g_sc);
    cudaGetSymbolAddress((void**)&at_,   g_at);
    cudaGetSymbolAddress((void**)&aos_,  g_aos);
    cudaGetSymbolAddress((void**)&x1_,   g_x1);
    cudaGetSymbolAddress((void**)&h2s_,  g_h2s);
    cudaGetSymbolAddress((void**)&w1T_,  g_w1T);
    cudaGetSymbolAddress((void**)&w3T_,  g_w3T);
    cudaGetSymbolAddress((void**)&w2T_,  g_w2T);
    cudaGetSymbolAddress((void**)&gs_,   g_gs);
    cudaGetSymbolAddress((void**)&ebuf_, g_ebuf);
    cudaGetSymbolAddress((void**)&lg_,   g_lg);
    cudaGetSymbolAddress((void**)&pr_,   g_pr);
    cudaGetSymbolAddress((void**)&tw_,   g_tw);
    cudaGetSymbolAddress((void**)&cnt_,  g_cnt);
    cudaGetSymbolAddress((void**)&list_, g_list);
    cudaGetSymbolAddress((void**)&te_,   g_te);
    cudaGetSymbolAddress((void**)&tp_,   g_tp);

    cudaFuncSetAttribute(hgemm<0,false>, cudaFuncAttributeMaxDynamicSharedMemorySize, SMEM1);
    cudaFuncSetAttribute(hgemm<1,false>, cudaFuncAttributeMaxDynamicSharedMemorySize, SMEM1);
    cudaFuncSetAttribute(hgemm<2,false>, cudaFuncAttributeMaxDynamicSharedMemorySize, SMEM1);
    cudaFuncSetAttribute(hgemm<4,false>, cudaFuncAttributeMaxDynamicSharedMemorySize, SMEM1);
    cudaFuncSetAttribute(hgemm2, cudaFuncAttributeMaxDynamicSharedMemorySize, SMEM2);

    const float eps = 1e-5f;
    const long DD = (long)D_ * D_;
    const long DK = (long)D_ * K2D;
    const long SK = (long)S_ * K2D;
    const long WUP = (long)H_ * K2D;   // w1/w3 per-expert stride
    const long WDN = (long)D_ * K2H;   // w2 per-expert stride
    const long GSZ = (long)CAP * K2H;  // gs per-expert stride
    const long EBZ = (long)CAP * D_;   // ebuf per-expert stride

    cudaStream_t s2;
    cudaStreamCreateWithFlags(&s2, cudaStreamNonBlocking);
    cudaEvent_t evFork, evQKV, evWo, evJoin, evT, evAtt, evTopk, evMoE2;
    cudaEventCreateWithFlags(&evFork, cudaEventDisableTiming);
    cudaEventCreateWithFlags(&evQKV,  cudaEventDisableTiming);
    cudaEventCreateWithFlags(&evWo,   cudaEventDisableTiming);
    cudaEventCreateWithFlags(&evJoin, cudaEventDisableTiming);
    cudaEventCreateWithFlags(&evT,    cudaEventDisableTiming);
    cudaEventCreateWithFlags(&evAtt,  cudaEventDisableTiming);
    cudaEventCreateWithFlags(&evTopk, cudaEventDisableTiming);
    cudaEventCreateWithFlags(&evMoE2, cudaEventDisableTiming);

    // main chain start
    ada_kernel<<<ADA6/128, 128>>>(adaln, adaw, adab, ada_);

    // fork immediately: ALL weight preps on side stream (input-only)
    cudaEventRecord(evFork, 0);
    cudaStreamWaitEvent(s2, evFork, 0);
    transQKV<<<dim3(D_/64, D_/64, 3), 256, 0, s2>>>(wq, wk, wv, wqkvT_);
    cudaEventRecord(evQKV, s2);
    transS<<<dim3(D_/64, D_/64, 1), 256, 0, s2>>>(wo, woT_, D_, D_, 0, 0);
    cudaEventRecord(evWo, s2);
    transS<<<dim3(H_/64, D_/64, E_), 256, 0, s2>>>(w1, w1T_, D_, H_, (long)D_*H_, WUP);
    transS<<<dim3(H_/64, D_/64, E_), 256, 0, s2>>>(w3, w3T_, D_, H_, (long)D_*H_, WUP);
    transS<<<dim3(D_/64, H_/64, E_), 256, 0, s2>>>(w2, w2T_, H_, D_, (long)H_*D_, WDN);
    cudaEventRecord(evJoin, s2);

    // main chain (ln overlaps transQKV)
    ln_kernel<<<BS_/8, 256>>>(x, nullptr, hs_, anw, anb, ada_ + D_, ada_, ADA6, eps,
        nullptr, nullptr, nullptr);
    cudaStreamWaitEvent(0, evQKV, 0);
    hgemm<4,false><<<dim3(16,24,1), 256, SMEM1>>>(hs_, 0, wqkvT_, 0, D_, 3*D_, BS_,
        nullptr, nullptr, q_, k_, 0, vs_, 1024, 0, nullptr, nullptr, 0);

    // q/k: fused stats(+cnt zero) + normalize-transpose-split
    qk_stats<<<2*BS_/8, 256>>>(q_, k_, mu_, rs_, cnt_, eps);
    transSN<<<dim3(D_/64, S_/64, 2*B_), 256>>>(q_, k_, qT_, kT_, qnw, qnb, knw, knb, mu_, rs_);

    // attention mid-chain: batches {0,1} on main, {2,3} on s2 (batch-disjoint)
    cudaEventRecord(evT, 0);
    cudaStreamWaitEvent(s2, evT, 0);
    hgemm<0,false><<<dim3(4,8,2), 256, SMEM1>>>(qT_, DK, kT_, DK,
        S_, D_, D_, nullptr, nullptr, sc_, nullptr, DD, nullptr, 0, 0, nullptr, nullptr, 0);
    softmax_kernel<<<2*D_/8, 256>>>(sc_, at_);
    hgemm<2,false><<<dim3(4,8,2), 256, SMEM1>>>(vs_, SK, at_, DK,
        D_, D_, S_, nullptr, nullptr, nullptr, nullptr, 0, aos_, D_, SK, nullptr, nullptr, 0);
    hgemm<0,false><<<dim3(4,8,2), 256, SMEM1, s2>>>(qT_ + 2*DK, DK, kT_ + 2*DK, DK,
        S_, D_, D_, nullptr, nullptr, sc_ + 2*DD, nullptr, DD, nullptr, 0, 0, nullptr, nullptr, 0);
    softmax_kernel<<<2*D_/8, 256, 0, s2>>>(sc_ + 2*DD, at_ + 2*DK);
    hgemm<2,false><<<dim3(4,8,2), 256, SMEM1, s2>>>(vs_ + 2*SK, SK, at_ + 2*DK, DK,
        D_, D_, S_, nullptr, nullptr, nullptr, nullptr, 0, aos_ + 2*SK, D_, SK, nullptr, nullptr, 0);
    cudaEventRecord(evAtt, s2);

    // join both halves + wo-prep, then x1 = x + gate_msa * (ao @ wo)
    cudaStreamWaitEvent(0, evAtt, 0);
    cudaStreamWaitEvent(0, evWo, 0);
    hgemm<1,false><<<dim3(16,8,1), 256, SMEM1>>>(aos_, 0, woT_, 0, D_, D_, BS_,
        nullptr, nullptr, x1_, nullptr, 0, nullptr, 0, 0, x, ada_ + 2L*D_, ADA6);

    // h2 = modulate(LN(x1), mlp): split out + fused router logits
    ln_kernel<<<BS_/8, 256>>>(x1_, nullptr, h2s_, fnw, fnb, ada_ + 4L*D_, ada_ + 3L*D_,
        ADA6, eps, rw, rb, lg_);

    // seq-norm + top-2 dispatch (exact fp32)
    seqnorm_kernel<<<B_*E_, 256>>>(lg_);
    topk_kernel<<<BS_/256, 256>>>(lg_, pr_, cnt_, list_, te_, tp_, tw_);
    cudaEventRecord(evTopk, 0);

    // MoE pipelined in two expert-halves:
    //   main: experts {0,1} up -> down ; s2: aux, experts {2,3} up -> down
    cudaStreamWaitEvent(0, evJoin, 0);                 // weights ready (main)
    hgemm2<<<dim3(CAP/128, H_/128, 2), 256, SMEM2>>>(h2s_, w1T_, w3T_, WUP,
        D_, H_, CAP, cnt_, list_, gs_, GSZ);
    hgemm<0,false><<<dim3(16,8,2), 256, SMEM1>>>(gs_, GSZ, w2T_, WDN,
        H_, D_, CAP, cnt_, nullptr, ebuf_, nullptr, EBZ, nullptr, 0, 0, nullptr, nullptr, 0);

    cudaStreamWaitEvent(s2, evTopk, 0);                // dispatch ready (s2; weights in-order)
    aux_kernel<<<1, 256, 0, s2>>>(pr_, out, (long)out_size);
    hgemm2<<<dim3(CAP/128, H_/128, 2), 256, SMEM2, s2>>>(h2s_, w1T_ + 2*WUP, w3T_ + 2*WUP, WUP,
        D_, H_, CAP, cnt_ + 2, list_ + 2L*CAP, gs_ + 2*GSZ, GSZ);
    hgemm<0,false><<<dim3(16,8,2), 256, SMEM1, s2>>>(gs_ + 2*GSZ, GSZ, w2T_ + 2*WDN, WDN,
        H_, D_, CAP, cnt_ + 2, nullptr, ebuf_ + 2*EBZ, nullptr, EBZ, nullptr, 0, 0, nullptr, nullptr, 0);
    cudaEventRecord(evMoE2, s2);

    // combine after both halves
    cudaStreamWaitEvent(0, evMoE2, 0);
    combine_kernel<<<(int)(BSD/1024), 256>>>(ebuf_, te_, tp_, tw_, out);

    cudaEventDestroy(evFork);
    cudaEventDestroy(evQKV);
    cudaEventDestroy(evWo);
    cudaEventDestroy(evJoin);
    cudaEventDestroy(evT);
    cudaEventDestroy(evAtt);
    cudaEventDestroy(evTopk);
    cudaEventDestroy(evMoE2);
    cudaStreamDestroy(s2);
}

// round 17
// speedup vs baseline: 1.0142x; 1.0142x over previous
#include <cuda_runtime.h>
#include <cuda_bf16.h>
#include <math.h>

typedef unsigned int u32;
typedef __nv_bfloat16 bf;

#define B_  4
#define S_  1024
#define D_  1024
#define E_  4
#define H_  2816
#define BS_ (B_*S_)
#define CAP BS_
#define ADA6 (6*D_)
#define BSD ((long)BS_*D_)
#define K2D 2048
#define K2H (2*H_)
#define STG1 49152
#define SMEM1 (4*STG1)
#define SMEM2 (4*STG1)

// ---------------- device scratch ----------------
__device__ __align__(16) float g_ada [B_*ADA6];
__device__ __align__(16) bf    g_hs  [(long)BS_*K2D];
__device__ __align__(16) bf    g_wqkvT[(long)3*D_*K2D];
__device__ __align__(16) bf    g_woT [(long)D_*K2D];
__device__ __align__(16) float g_q   [BS_*D_];
__device__ __align__(16) float g_k   [BS_*D_];
__device__ __align__(16) float g_mu  [2*BS_];
__device__ __align__(16) float g_rs  [2*BS_];
__device__ __align__(16) bf    g_qT  [(long)B_*D_*K2D];
__device__ __align__(16) bf    g_kT  [(long)B_*D_*K2D];
__device__ __align__(16) bf    g_vs  [(long)BS_*K2D];
__device__ __align__(16) float g_sc  [(long)B_*D_*D_];
__device__ __align__(16) bf    g_at  [(long)B_*D_*K2D];
__device__ __align__(16) bf    g_aos [(long)BS_*K2D];
__device__ __align__(16) float g_x1  [BS_*D_];
__device__ __align__(16) bf    g_h2s [(long)BS_*K2D];
__device__ __align__(16) bf    g_w1T [(long)E_*H_*K2D];
__device__ __align__(16) bf    g_w3T [(long)E_*H_*K2D];
__device__ __align__(16) bf    g_w2T [(long)E_*D_*K2H];
__device__ __align__(16) bf    g_gs  [(long)E_*CAP*K2H];
__device__ __align__(16) float g_ebuf[(long)E_*CAP*D_];
__device__ __align__(16) float g_lg  [BS_*E_];
__device__ __align__(16) float g_pr  [BS_*E_];
__device__ int   g_cnt [E_];
__device__ int   g_list[E_*CAP];
__device__ int   g_te  [BS_*2];
__device__ int   g_tp  [BS_*2];
__device__ __align__(16) float g_tw  [BS_*2];

// ---------------- helpers ----------------
__device__ __forceinline__ u32 smem_u32(const void* p) {
    u32 a;
    asm("{ .reg .u64 t; cvta.to.shared.u64 t, %1; cvt.u32.u64 %0, t; }" : "=r"(a) : "l"(p));
    return a;
}
__device__ __forceinline__ u32 swz(u32 o) { return o ^ ((o >> 3) & 0x70); }
__device__ __forceinline__ void bsplit(float v, bf& h, bf& l) {
    h = __float2bfloat16(v);
    l = __float2bfloat16(v - __bfloat162float(h));
}
__device__ __forceinline__ u32 pk2(bf a, bf b) {
    return (u32)__bfloat16_as_ushort(a) | ((u32)__bfloat16_as_ushort(b) << 16);
}
#define CP16(dst, src) asm volatile("cp.async.cg.shared.global [%0], [%1], 16;" :: "r"(dst), "l"(src))
#define CP_COMMIT()    asm volatile("cp.async.commit_group;")
#define CP_WAIT2()     asm volatile("cp.async.wait_group 2;")
#define LDM4(r, ad) asm volatile("ldmatrix.sync.aligned.m8n8.x4.shared.b16 {%0,%1,%2,%3}, [%4];" \
    : "=r"((r)[0]), "=r"((r)[1]), "=r"((r)[2]), "=r"((r)[3]) : "r"(ad))
#define MMA(c, a, b0, b1) asm volatile( \
    "mma.sync.aligned.m16n8k16.row.col.f32.bf16.bf16.f32 " \
    "{%0,%1,%2,%3}, {%4,%5,%6,%7}, {%8,%9}, {%0,%1,%2,%3};" \
    : "+f"((c)[0]), "+f"((c)[1]), "+f"((c)[2]), "+f"((c)[3]) \
    : "r"((a)[0]), "r"((a)[1]), "r"((a)[2]), "r"((a)[3]), "r"(b0), "r"(b1))

// ============ bf16 split GEMM: C[M,N] = A[M,2K](3seg) * B[N,2K](3seg)^T ============
template<int EPI, bool GATHER>
__global__ void __launch_bounds__(256, 1) hgemm(
    const bf* __restrict__ A, long aZ,
    const bf* __restrict__ Bm, long bZ,
    int Kr, int N, int Mcap,
    const int* __restrict__ counts, const int* __restrict__ list,
    float* __restrict__ Cf, float* __restrict__ Ck, long cZ,
    bf* __restrict__ Cs, int outW, long csZ,
    const float* __restrict__ aux,
    const float* __restrict__ gate, int gateStride)
{
    extern __shared__ __align__(16) char smem[];
    const int z = blockIdx.z;
    const int Meff = counts ? counts[z] : Mcap;
    const int m0 = blockIdx.x * 256;
    if (m0 >= Meff) return;
    const int n0 = blockIdx.y * 128;
    const int tid = threadIdx.x, wid = tid >> 5, lane = tid & 31;
    const int wm = wid >> 1, wn = wid & 1;
    const u32 sb = smem_u32(smem);
    const long K2 = 2L * Kr;

    const bf* Az = A + (long)z * aZ;
    const bf* Bz = Bm + (long)z * bZ;

    long aRow[8];
    int  jA = tid & 7;
#pragma unroll
    for (int i = 0; i < 8; i++) {
        int r = (i * 256 + tid) >> 3;
        int gm = m0 + r; if (gm > Meff - 1) gm = Meff - 1;
        aRow[i] = GATHER ? (long)list[(long)z * CAP + gm] : (long)gm;
    }
    u32 dA[8], dB[4];
#pragma unroll
    for (int i = 0; i < 8; i++) { int r = (i * 256 + tid) >> 3; dA[i] = swz((u32)(r * 128 + jA * 16)); }
#pragma unroll
    for (int i = 0; i < 4; i++) { int r = (i * 256 + tid) >> 3; dB[i] = swz((u32)(r * 128 + jA * 16)); }

    float acc[4][8][4];
#pragma unroll
    for (int a = 0; a < 4; a++)
#pragma unroll
        for (int b = 0; b < 8; b++)
#pragma unroll
            for (int c = 0; c < 4; c++) acc[a][b][c] = 0.f;

    const int seglen = Kr >> 6;
    const int NC = 3 * seglen;

    auto issue = [&](int c) {
        int seg = c / seglen;
        int kin = (c - seg * seglen) << 6;
        int aOff = (seg == 2 ? Kr : 0) + kin + jA * 8;
        int bOff = (seg == 1 ? Kr : 0) + kin + jA * 8;
        u32 base = sb + (u32)(c & 3) * STG1;
#pragma unroll
        for (int i = 0; i < 8; i++)
            CP16(base + dA[i], Az + aRow[i] * K2 + aOff);
#pragma unroll
        for (int i = 0; i < 4; i++) {
            int r = (i * 256 + tid) >> 3;
            CP16(base + 32768 + dB[i], Bz + (long)(n0 + r) * K2 + bOff);
        }
    };

    issue(0); CP_COMMIT();
    issue(1); CP_COMMIT();
    issue(2); CP_COMMIT();

    for (int c = 0; c < NC; c++) {
        CP_WAIT2();
        __syncthreads();
        if (c + 3 < NC) issue(c + 3);
        CP_COMMIT();
        u32 aB = sb + (u32)(c & 3) * STG1, bB = aB + 32768;
#pragma unroll
        for (int s = 0; s < 4; s++) {
            u32 afr[4][4], bfr[4][4];
#pragma unroll
            for (int mi = 0; mi < 4; mi++) {
                int row = wm * 64 + mi * 16 + (lane & 7) + ((lane >> 3) & 1) * 8;
                int kb = s * 32 + (lane >> 4) * 16;
                LDM4(afr[mi], aB + swz((u32)(row * 128 + kb)));
            }
#pragma unroll
            for (int ni = 0; ni < 4; ni++) {
                int nrow = wn * 64 + ni * 16 + (lane & 7) + (lane >> 4) * 8;
                int kb = s * 32 + ((lane >> 3) & 1) * 16;
                LDM4(bfr[ni], bB + swz((u32)(nrow * 128 + kb)));
            }
#pragma unroll
            for (int mi = 0; mi < 4; mi++)
#pragma unroll
                for (int nj = 0; nj < 8; nj++)
                    MMA(acc[mi][nj], afr[mi], bfr[nj >> 1][(nj & 1) * 2], bfr[nj >> 1][(nj & 1) * 2 + 1]);
        }
    }

#pragma unroll
    for (int mi = 0; mi < 4; mi++) {
#pragma unroll
        for (int half = 0; half < 2; half++) {
            int row = m0 + wm * 64 + mi * 16 + (lane >> 2) + half * 8;
            if (row >= Meff) continue;
#pragma unroll
            for (int nj = 0; nj < 8; nj++) {
                int col = n0 + wn * 64 + nj * 8 + (lane & 3) * 2;
                float v0 = acc[mi][nj][half * 2], v1 = acc[mi][nj][half * 2 + 1];
                if (EPI == 0) {
                    *(float2*)(Cf + (long)z * cZ + (long)row * N + col) = make_float2(v0, v1);
                } else if (EPI == 1) {
                    int bb = row >> 10;
                    const float2 rs = *(const float2*)(aux + (long)row * N + col);
                    const float* gv = gate + (long)bb * gateStride + col;
                    *(float2*)(Cf + (long)row * N + col) = make_float2(rs.x + gv[0] * v0, rs.y + gv[1] * v1);
                } else if (EPI == 4) {
                    if (col < 1024) {
                        *(float2*)(Cf + (long)row * 1024 + col) = make_float2(v0, v1);
                    } else if (col < 2048) {
                        *(float2*)(Ck + (long)row * 1024 + (col - 1024)) = make_float2(v0, v1);
                    } else {
                        int cc = col - 2048;
                        bf h0, l0, h1, l1;
                        bsplit(v0, h0, l0); bsplit(v1, h1, l1);
                        bf* o = Cs + (long)row * 2048 + cc;
                        *(u32*)(o) = pk2(h0, h1);
                        *(u32*)(o + 1024) = pk2(l0, l1);
                    }
                } else {
                    bf h0, l0, h1, l1;
                    bsplit(v0, h0, l0); bsplit(v1, h1, l1);
                    bf* o = Cs + (long)z * csZ + (long)row * 2 * outW + col;
                    *(u32*)(o) = pk2(h0, h1);
                    *(u32*)(o + outW) = pk2(l0, l1);
                }
            }
        }
    }
}

// ============ dual-B GEMM (MoE up, fused): gs = split(sin(A*B1^T) * (A*B2^T)) ============
__global__ void __launch_bounds__(256, 1) hgemm2(
    const bf* __restrict__ A,
    const bf* __restrict__ B1m, const bf* __restrict__ B2m, long bZ,
    int Kr, int N, int Mcap,
    const int* __restrict__ counts, const int* __restrict__ list,
    bf* __restrict__ Cs, long csZ)
{
    extern __shared__ __align__(16) char smem[];
    const int z = blockIdx.z;
    const int Meff = counts[z];
    const int m0 = blockIdx.x * 128;
    if (m0 >= Meff) return;
    const int n0 = blockIdx.y * 128;
    const int tid = threadIdx.x, wid = tid >> 5, lane = tid & 31;
    const int wm = wid >> 2, wn = wid & 3;
    const u32 sb = smem_u32(smem);
    const long K2 = 2L * Kr;

    const bf* B1z = B1m + (long)z * bZ;
    const bf* B2z = B2m + (long)z * bZ;

    long aRow[4];
    int jA = tid & 7;
#pragma unroll
    for (int i = 0; i < 4; i++) {
        int r = (i * 256 + tid) >> 3;
        int gm = m0 + r; if (gm > Meff - 1) gm = Meff - 1;
        aRow[i] = (long)list[(long)z * CAP + gm];
    }
    u32 dT[4];
#pragma unroll
    for (int i = 0; i < 4; i++) { int r = (i * 256 + tid) >> 3; dT[i] = swz((u32)(r * 128 + jA * 16)); }

    float acc1[4][4][4], acc2[4][4][4];
#pragma unroll
    for (int a = 0; a < 4; a++)
#pragma unroll
        for (int b = 0; b < 4; b++)
#pragma unroll
            for (int c = 0; c < 4; c++) { acc1[a][b][c] = 0.f; acc2[a][b][c] = 0.f; }

    const int seglen = Kr >> 6;
    const int NC = 3 * seglen;

    auto issue = [&](int c) {
        int seg = c / seglen;
        int kin = (c - seg * seglen) << 6;
        int aOff = (seg == 2 ? Kr : 0) + kin + jA * 8;
        int bOff = (seg == 1 ? Kr : 0) + kin + jA * 8;
        u32 base = sb + (u32)(c & 3) * STG1;
#pragma unroll
        for (int i = 0; i < 4; i++) {
            int r = (i * 256 + tid) >> 3;
            CP16(base + dT[i], A + aRow[i] * K2 + aOff);
            CP16(base + 16384 + dT[i], B1z + (long)(n0 + r) * K2 + bOff);
            CP16(base + 32768 + dT[i], B2z + (long)(n0 + r) * K2 + bOff);
        }
    };

    issue(0); CP_COMMIT();
    issue(1); CP_COMMIT();
    issue(2); CP_COMMIT();

    for (int c = 0; c < NC; c++) {
        CP_WAIT2();
        __syncthreads();
        if (c + 3 < NC) issue(c + 3);
        CP_COMMIT();
        u32 aB = sb + (u32)(c & 3) * STG1, b1B = aB + 16384, b2B = aB + 32768;
#pragma unroll
        for (int s = 0; s < 4; s++) {
            u32 afr[4][4], bfr1[2][4], bfr2[2][4];
#pragma unroll
            for (int mi = 0; mi < 4; mi++) {
                int row = wm * 64 + mi * 16 + (lane & 7) + ((lane >> 3) & 1) * 8;
                int kb = s * 32 + (lane >> 4) * 16;
                LDM4(afr[mi], aB + swz((u32)(row * 128 + kb)));
            }
#pragma unroll
            for (int bi = 0; bi < 2; bi++) {
                int nrow = wn * 32 + bi * 16 + (lane & 7) + (lane >> 4) * 8;
                int kb = s * 32 + ((lane >> 3) & 1) * 16;
                LDM4(bfr1[bi], b1B + swz((u32)(nrow * 128 + kb)));
                LDM4(bfr2[bi], b2B + swz((u32)(nrow * 128 + kb)));
            }
#pragma unroll
            for (int mi = 0; mi < 4; mi++)
#pragma unroll
                for (int nj = 0; nj < 4; nj++) {
                    MMA(acc1[mi][nj], afr[mi], bfr1[nj >> 1][(nj & 1) * 2], bfr1[nj >> 1][(nj & 1) * 2 + 1]);
                    MMA(acc2[mi][nj], afr[mi], bfr2[nj >> 1][(nj & 1) * 2], bfr2[nj >> 1][(nj & 1) * 2 + 1]);
                }
        }
    }

#pragma unroll
    for (int mi = 0; mi < 4; mi++) {
#pragma unroll
        for (int half = 0; half < 2; half++) {
            int row = m0 + wm * 64 + mi * 16 + (lane >> 2) + half * 8;
            if (row >= Meff) continue;
#pragma unroll
            for (int nj = 0; nj < 4; nj++) {
                int col = n0 + wn * 32 + nj * 8 + (lane & 3) * 2;
                float v0 = sinf(acc1[mi][nj][half * 2]) * acc2[mi][nj][half * 2];
                float v1 = sinf(acc1[mi][nj][half * 2 + 1]) * acc2[mi][nj][half * 2 + 1];
                bf h0, l0, h1, l1;
                bsplit(v0, h0, l0); bsplit(v1, h1, l1);
                bf* o = Cs + (long)z * csZ + (long)row * (long)(2 * N) + col;
                *(u32*)(o) = pk2(h0, h1);
                *(u32*)(o + N) = pk2(l0, l1);
            }
        }
    }
}

// ---------------- prep kernels ----------------
__global__ void __launch_bounds__(256) transS(const float* __restrict__ in, bf* __restrict__ out,
                                              int R, int C, long inZ, long outZ)
{
    __shared__ float t[64][65];
    int z = blockIdx.z;
    const float* iz = in + (long)z * inZ;
    bf* oz = out + (long)z * outZ;
    int c0 = blockIdx.x * 64, r0 = blockIdx.y * 64;
    int tid = threadIdx.x;
    int lc = (tid & 15) * 4, lr = tid >> 4;
#pragma unroll
    for (int p = 0; p < 4; p++) {
        int r = lr + p * 16;
        float4 v = *(const float4*)&iz[(long)(r0 + r) * C + c0 + lc];
        t[r][lc] = v.x; t[r][lc + 1] = v.y; t[r][lc + 2] = v.z; t[r][lc + 3] = v.w;
    }
    __syncthreads();
    int wr = (tid & 15) * 4, wc = tid >> 4;
#pragma unroll
    for (int p = 0; p < 4; p++) {
        int c = wc + p * 16;
        float v0 = t[wr + 0][c], v1 = t[wr + 1][c], v2 = t[wr + 2][c], v3 = t[wr + 3][c];
        bf h0, l0, h1, l1, h2, l2, h3, l3;
        bsplit(v0, h0, l0); bsplit(v1, h1, l1); bsplit(v2, h2, l2); bsplit(v3, h3, l3);
        long base = (long)(c0 + c) * 2 * R + r0 + wr;
        uint2 hh, ll;
        hh.x = pk2(h0, h1); hh.y = pk2(h2, h3);
        ll.x = pk2(l0, l1); ll.y = pk2(l2, l3);
        *(uint2*)&oz[base] = hh;
        *(uint2*)&oz[base + R] = ll;
    }
}

__global__ void __launch_bounds__(256) transQKV(const float* __restrict__ wq,
    const float* __restrict__ wk, const float* __restrict__ wv, bf* __restrict__ out)
{
    __shared__ float t[64][65];
    int which = blockIdx.z;
    const float* iz = which == 0 ? wq : (which == 1 ? wk : wv);
    bf* oz = out + (long)which * D_ * K2D;
    int c0 = blockIdx.x * 64, r0 = blockIdx.y * 64;
    int tid = threadIdx.x;
    int lc = (tid & 15) * 4, lr = tid >> 4;
#pragma unroll
    for (int p = 0; p < 4; p++) {
        int r = lr + p * 16;
        float4 v = *(const float4*)&iz[(long)(r0 + r) * D_ + c0 + lc];
        t[r][lc] = v.x; t[r][lc + 1] = v.y; t[r][lc + 2] = v.z; t[r][lc + 3] = v.w;
    }
    __syncthreads();
    int wr = (tid & 15) * 4, wc = tid >> 4;
#pragma unroll
    for (int p = 0; p < 4; p++) {
        int c = wc + p * 16;
        float v0 = t[wr + 0][c], v1 = t[wr + 1][c], v2 = t[wr + 2][c], v3 = t[wr + 3][c];
        bf h0, l0, h1, l1, h2, l2, h3, l3;
        bsplit(v0, h0, l0); bsplit(v1, h1, l1); bsplit(v2, h2, l2); bsplit(v3, h3, l3);
        long base = (long)(c0 + c) * 2 * D_ + r0 + wr;
        uint2 hh, ll;
        hh.x = pk2(h0, h1); hh.y = pk2(h2, h3);
        ll.x = pk2(l0, l1); ll.y = pk2(l2, l3);
        *(uint2*)&oz[base] = hh;
        *(uint2*)&oz[base + D_] = ll;
    }
}

// per-row mean/rstd for q_/k_; also zeroes cnt (block 0)
__global__ void __launch_bounds__(256) qk_stats(const float* __restrict__ q,
    const float* __restrict__ k, float* __restrict__ mu, float* __restrict__ rs,
    int* __restrict__ cnt, float eps)
{
    if (blockIdx.x == 0 && threadIdx.x < E_) cnt[threadIdx.x] = 0;
    int row = blockIdx.x * 8 + (threadIdx.x >> 5);
    int lane = threadIdx.x & 31;
    const float* src = (row < BS_) ? (q + (long)row * D_) : (k + (long)(row - BS_) * D_);
    float s1 = 0.f, s2 = 0.f;
#pragma unroll
    for (int j = 0; j < 8; j++) {
        float4 v = *(const float4*)&src[j * 128 + lane * 4];
        s1 += v.x + v.y + v.z + v.w;
        s2 += v.x * v.x + v.y * v.y + v.z * v.z + v.w * v.w;
    }
#pragma unroll
    for (int o = 16; o; o >>= 1) {
        s1 += __shfl_xor_sync(0xffffffffu, s1, o);
        s2 += __shfl_xor_sync(0xffffffffu, s2, o);
    }
    if (lane == 0) {
        float mean = s1 * (1.f / D_);
        float var = s2 * (1.f / D_) - mean * mean;
        mu[row] = mean;
        rs[row] = rsqrtf(var + eps);
    }
}

// fused normalize + transpose + split for q and k
__global__ void __launch_bounds__(256) transSN(const float* __restrict__ qin,
    const float* __restrict__ kin, bf* __restrict__ qout, bf* __restrict__ kout,
    const float* __restrict__ qw, const float* __restrict__ qb,
    const float* __restrict__ kw, const float* __restrict__ kb,
    const float* __restrict__ mu, const float* __restrict__ rs)
{
    __shared__ float t[64][65];
    int z = blockIdx.z;
    int isK = z >= B_;
    int b = z & 3;
    const float* iz = (isK ? kin : qin) + (long)b * S_ * D_;
    bf* oz = (isK ? kout : qout) + (long)b * D_ * K2D;
    const float* w = isK ? kw : qw;
    const float* bb = isK ? kb : qb;
    int statOff = (isK ? BS_ : 0) + b * S_;
    int c0 = blockIdx.x * 64, r0 = blockIdx.y * 64;
    int tid = threadIdx.x;
    int lc = (tid & 15) * 4, lr = tid >> 4;
    float4 wv = *(const float4*)&w[c0 + lc];
    float4 bv = *(const float4*)&bb[c0 + lc];
#pragma unroll
    for (int p = 0; p < 4; p++) {
        int r = lr + p * 16;
        float m = mu[statOff + r0 + r];
        float rv = rs[statOff + r0 + r];
        float4 v = *(const float4*)&iz[(long)(r0 + r) * D_ + c0 + lc];
        t[r][lc]     = (v.x - m) * rv * wv.x + bv.x;
        t[r][lc + 1] = (v.y - m) * rv * wv.y + bv.y;
        t[r][lc + 2] = (v.z - m) * rv * wv.z + bv.z;
        t[r][lc + 3] = (v.w - m) * rv * wv.w + bv.w;
    }
    __syncthreads();
    int wr = (tid & 15) * 4, wc = tid >> 4;
#pragma unroll
    for (int p = 0; p < 4; p++) {
        int c = wc + p * 16;
        float v0 = t[wr + 0][c], v1 = t[wr + 1][c], v2 = t[wr + 2][c], v3 = t[wr + 3][c];
        bf h0, l0, h1, l1, h2, l2, h3, l3;
        bsplit(v0, h0, l0); bsplit(v1, h1, l1); bsplit(v2, h2, l2); bsplit(v3, h3, l3);
        long base = (long)(c0 + c) * K2D + r0 + wr;
        uint2 hh, ll;
        hh.x = pk2(h0, h1); hh.y = pk2(h2, h3);
        ll.x = pk2(l0, l1); ll.y = pk2(l2, l3);
        *(uint2*)&oz[base] = hh;
        *(uint2*)&oz[base + S_] = ll;
    }
}

__global__ void __launch_bounds__(128) ada_kernel(const float* __restrict__ adaln,
    const float* __restrict__ W, const float* __restrict__ bias, float* __restrict__ ada)
{
    __shared__ float s[B_ * D_];
    int col = blockIdx.x * 128 + threadIdx.x;
    for (int i = threadIdx.x; i < B_ * D_; i += 128) {
        float v = adaln[i];
        s[i] = v / (1.f + expf(-v));
    }
    __syncthreads();
    float a0 = 0.f, a1 = 0.f, a2 = 0.f, a3 = 0.f;
    for (int k = 0; k < D_; k++) {
        float w = W[(long)k * ADA6 + col];
        a0 = fmaf(s[k], w, a0); a1 = fmaf(s[D_ + k], w, a1);
        a2 = fmaf(s[2 * D_ + k], w, a2); a3 = fmaf(s[3 * D_ + k], w, a3);
    }
    float bv = bias[col];
    ada[col] = a0 + bv; ada[ADA6 + col] = a1 + bv;
    ada[2L * ADA6 + col] = a2 + bv; ada[3L * ADA6 + col] = a3 + bv;
}

// LN width 1024: warp-per-row; optional fp32 out, split out, and fused router logits
__global__ void __launch_bounds__(256) ln_kernel(const float* __restrict__ in,
    float* __restrict__ outF, bf* __restrict__ outS,
    const float* __restrict__ w, const float* __restrict__ b,
    const float* __restrict__ scale, const float* __restrict__ shift,
    int adaStride, float eps,
    const float* __restrict__ rw, const float* __restrict__ rb, float* __restrict__ lg)
{
    int row = blockIdx.x * 8 + (threadIdx.x >> 5);
    int lane = threadIdx.x & 31;
    const float* xr = in + (long)row * D_;
    float4 v[8];
    float s1 = 0.f, s2 = 0.f;
#pragma unroll
    for (int j = 0; j < 8; j++) {
        v[j] = *(const float4*)&xr[j * 128 + lane * 4];
        s1 += v[j].x + v[j].y + v[j].z + v[j].w;
        s2 += v[j].x * v[j].x + v[j].y * v[j].y + v[j].z * v[j].z + v[j].w * v[j].w;
    }
#pragma unroll
    for (int o = 16; o; o >>= 1) {
        s1 += __shfl_xor_sync(0xffffffffu, s1, o);
        s2 += __shfl_xor_sync(0xffffffffu, s2, o);
    }
    float mean = s1 * (1.f / D_);
    float var = s2 * (1.f / D_) - mean * mean;
    float rsv = rsqrtf(var + eps);
    int bb = row >> 10;
#pragma unroll
    for (int j = 0; j < 8; j++) {
        int c0 = j * 128 + lane * 4;
        float4 wv = *(const float4*)&w[c0];
        float4 bv = *(const float4*)&b[c0];
        float o0 = (v[j].x - mean) * rsv * wv.x + bv.x;
        float o1 = (v[j].y - mean) * rsv * wv.y + bv.y;
        float o2 = (v[j].z - mean) * rsv * wv.z + bv.z;
        float o3 = (v[j].w - mean) * rsv * wv.w + bv.w;
        if (scale) {
            float4 sv = *(const float4*)&scale[(long)bb * adaStride + c0];
            float4 hv = *(const float4*)&shift[(long)bb * adaStride + c0];
            o0 = o0 * (1.f + sv.x) + hv.x;
            o1 = o1 * (1.f + sv.y) + hv.y;
            o2 = o2 * (1.f + sv.z) + hv.z;
            o3 = o3 * (1.f + sv.w) + hv.w;
        }
        v[j] = make_float4(o0, o1, o2, o3);
        if (outF)
            *(float4*)&outF[(long)row * D_ + c0] = v[j];
        if (outS) {
            bf h0, l0, h1, l1, h2, l2, h3, l3;
            bsplit(o0, h0, l0); bsplit(o1, h1, l1);
            bsplit(o2, h2, l2); bsplit(o3, h3, l3);
            bf* os = outS + (long)row * K2D;
            uint2 hh, ll;
            hh.x = pk2(h0, h1); hh.y = pk2(h2, h3);
            ll.x = pk2(l0, l1); ll.y = pk2(l2, l3);
            *(uint2*)&os[c0] = hh;
            *(uint2*)&os[D_ + c0] = ll;
        }
    }
    if (rw) {
        float a0 = 0.f, a1 = 0.f, a2 = 0.f, a3 = 0.f;
#pragma unroll
        for (int j = 0; j < 8; j++) {
            float hvv[4] = { v[j].x, v[j].y, v[j].z, v[j].w };
#pragma unroll
            for (int u = 0; u < 4; u++) {
                int k = j * 128 + lane * 4 + u;
                float4 wv = *(const float4*)&rw[(long)k * 4];
                a0 = fmaf(hvv[u], wv.x, a0); a1 = fmaf(hvv[u], wv.y, a1);
                a2 = fmaf(hvv[u], wv.z, a2); a3 = fmaf(hvv[u], wv.w, a3);
            }
        }
#pragma unroll
        for (int o = 16; o; o >>= 1) {
            a0 += __shfl_xor_sync(0xffffffffu, a0, o);
            a1 += __shfl_xor_sync(0xffffffffu, a1, o);
            a2 += __shfl_xor_sync(0xffffffffu, a2, o);
            a3 += __shfl_xor_sync(0xffffffffu, a3, o);
        }
        if (lane == 0) {
            lg[(long)row * 4 + 0] = a0 + rb[0];
            lg[(long)row * 4 + 1] = a1 + rb[1];
            lg[(long)row * 4 + 2] = a2 + rb[2];
            lg[(long)row * 4 + 3] = a3 + rb[3];
        }
    }
}

__global__ void __launch_bounds__(256) softmax_kernel(const float* __restrict__ p, bf* __restrict__ outS) {
    int row = blockIdx.x * 8 + (threadIdx.x >> 5);
    int lane = threadIdx.x & 31;
    const float* r = p + (long)row * D_;
    float4 v[8];
    float m = -1e30f;
#pragma unroll
    for (int j = 0; j < 8; j++) {
        v[j] = *(const float4*)&r[j * 128 + lane * 4];
        m = fmaxf(m, fmaxf(fmaxf(v[j].x, v[j].y), fmaxf(v[j].z, v[j].w)));
    }
#pragma unroll
    for (int o = 16; o; o >>= 1) m = fmaxf(m, __shfl_xor_sync(0xffffffffu, m, o));
    float s = 0.f;
#pragma unroll
    for (int j = 0; j < 8; j++) {
        v[j].x = expf(v[j].x - m); v[j].y = expf(v[j].y - m);
        v[j].z = expf(v[j].z - m); v[j].w = expf(v[j].w - m);
        s += v[j].x + v[j].y + v[j].z + v[j].w;
    }
#pragma unroll
    for (int o = 16; o; o >>= 1) s += __shfl_xor_sync(0xffffffffu, s, o);
    float inv = 1.f / s;
    bf* os = outS + (long)row * K2D;
#pragma unroll
    for (int j = 0; j < 8; j++) {
        int c0 = j * 128 + lane * 4;
        bf h0, l0, h1, l1, h2, l2, h3, l3;
        bsplit(v[j].x * inv, h0, l0); bsplit(v[j].y * inv, h1, l1);
        bsplit(v[j].z * inv, h2, l2); bsplit(v[j].w * inv, h3, l3);
        uint2 hh, ll;
        hh.x = pk2(h0, h1); hh.y = pk2(h2, h3);
        ll.x = pk2(l0, l1); ll.y = pk2(l2, l3);
        *(uint2*)&os[c0] = hh;
        *(uint2*)&os[D_ + c0] = ll;
    }
}

__global__ void __launch_bounds__(256) seqnorm_kernel(float* __restrict__ lg) {
    int b = blockIdx.x >> 2, e = blockIdx.x & 3;
    int t = threadIdx.x;
    float s = 0.f;
    for (int i = t; i < S_; i += 256) {
        float v = lg[((long)(b * S_ + i)) * 4 + e];
        s += v * v;
    }
    __shared__ float sm[8];
#pragma unroll
    for (int o = 16; o; o >>= 1) s += __shfl_down_sync(0xffffffffu, s, o);
    if ((t & 31) == 0) sm[t >> 5] = s;
    __syncthreads();
    if (t == 0) {
        float a = 0.f;
        for (int i = 0; i < 8; i++) a += sm[i];
        sm[0] = 1.f / fmaxf(sqrtf(a), 1e-12f);
    }
    __syncthreads();
    float sc = sm[0];
    for (int i = t; i < S_; i += 256) lg[((long)(b * S_ + i)) * 4 + e] *= sc;
}

__global__ void topk_kernel(const float* __restrict__ lg, float* __restrict__ pr,
    int* __restrict__ cnt, int* __restrict__ list,
    int* __restrict__ te, int* __restrict__ tp, float* __restrict__ tw)
{
    int tok = blockIdx.x * 256 + threadIdx.x;
    if (tok >= BS_) return;
    float l[4];
#pragma unroll
    for (int e = 0; e < 4; e++) l[e] = lg[(long)tok * 4 + e];
    float m = fmaxf(fmaxf(l[0], l[1]), fmaxf(l[2], l[3]));
    float p[4]; float s = 0.f;
#pragma unroll
    for (int e = 0; e < 4; e++) { p[e] = expf(l[e] - m); s += p[e]; }
    float inv = 1.f / s;
#pragma unroll
    for (int e = 0; e < 4; e++) { p[e] *= inv; pr[(long)tok * 4 + e] = p[e]; }
    int a0 = 0;
#pragma unroll
    for (int e = 1; e < 4; e++) if (p[e] > p[a0]) a0 = e;
    int a1 = -1; float pb = -1.f;
#pragma unroll
    for (int e = 0; e < 4; e++) if (e != a0 && p[e] > pb) { pb = p[e]; a1 = e; }
    int s0 = atomicAdd(&cnt[a0], 1); list[a0 * CAP + s0] = tok;
    int s1 = atomicAdd(&cnt[a1], 1); list[a1 * CAP + s1] = tok;
    te[2 * tok] = a0;     tp[2 * tok] = s0;     tw[2 * tok] = p[a0];
    te[2 * tok + 1] = a1; tp[2 * tok + 1] = s1; tw[2 * tok + 1] = p[a1];
}

// vectorized combine: 4 elems/thread
__global__ void combine_kernel(const float* __restrict__ ebuf,
    const int* __restrict__ te, const int* __restrict__ tp,
    const float* __restrict__ tw, float* __restrict__ out)
{
    long gid = ((long)blockIdx.x * 256 + threadIdx.x) * 4;
    int tok = (int)(gid >> 10);
    int d = (int)(gid & 1023);
    int e0 = te[2 * tok], e1 = te[2 * tok + 1];
    float w0 = tw[2 * tok], w1 = tw[2 * tok + 1];
    const float4 a = *(const float4*)&ebuf[((long)e0 * CAP + tp[2 * tok]) * D_ + d];
    const float4 b = *(const float4*)&ebuf[((long)e1 * CAP + tp[2 * tok + 1]) * D_ + d];
    float4 o;
    o.x = w0 * a.x + w1 * b.x;
    o.y = w0 * a.y + w1 * b.y;
    o.z = w0 * a.z + w1 * b.z;
    o.w = w0 * a.w + w1 * b.w;
    *(float4*)&out[gid] = o;
}

__global__ void __launch_bounds__(256) aux_kernel(const float* __restrict__ pr,
                                                  float* __restrict__ out, long out_size)
{
    int t = threadIdx.x;
    float acc = 0.f;
    for (int i = t; i < S_ * E_; i += 256) {
        int s = i >> 2, e = i & 3;
        float av = 0.f;
#pragma unroll
        for (int b = 0; b < B_; b++) av += pr[((long)(b * S_ + s)) * 4 + e];
        av *= 0.25f;
        float d = 0.25f - av;
        acc += d * d;
    }
    __shared__ float sm[8];
#pragma unroll
    for (int o = 16; o; o >>= 1) acc += __shfl_xor_sync(0xffffffffu, acc, o);
    if ((t & 31) == 0) sm[t >> 5] = acc;
    __syncthreads();
    if (t == 0) {
        float a = 0.f;
        for (int i = 0; i < 8; i++) a += sm[i];
        for (long i = BSD; i < out_size; i++) out[i] = a;
    }
}

// ---------------- host launcher ----------------
extern "C" void kernel_launch(void* const* d_in, const int* in_sizes, int n_in,
                              void* d_out, int out_size)
{
    (void)in_sizes; (void)n_in;
    const float* x     = (const float*)d_in[0];
    const float* adaln = (const float*)d_in[2];
    const float* wq    = (const float*)d_in[3];
    const float* wk    = (const float*)d_in[4];
    const float* wv    = (const float*)d_in[5];
    const float* wo    = (const float*)d_in[6];
    const float* qnw   = (const float*)d_in[7];
    const float* qnb   = (const float*)d_in[8];
    const float* knw   = (const float*)d_in[9];
    const float* knb   = (const float*)d_in[10];
    const float* anw   = (const float*)d_in[11];
    const float* anb   = (const float*)d_in[12];
    const float* fnw   = (const float*)d_in[13];
    const float* fnb   = (const float*)d_in[14];
    const float* w1    = (const float*)d_in[15];
    const float* w2    = (const float*)d_in[16];
    const float* w3    = (const float*)d_in[17];
    const float* rw    = (const float*)d_in[18];
    const float* rb    = (const float*)d_in[19];
    const float* adaw  = (const float*)d_in[20];
    const float* adab  = (const float*)d_in[21];
    float* out = (float*)d_out;

    float *ada_, *q_, *k_, *mu_, *rs_, *sc_, *x1_, *lg_, *pr_, *ebuf_, *tw_;
    bf *hs_, *wqkvT_, *woT_, *qT_, *kT_, *vs_, *at_, *aos_, *h2s_, *w1T_, *w3T_, *w2T_, *gs_;
    int *cnt_, *list_, *te_, *tp_;
    cudaGetSymbolAddress((void**)&ada_,  g_ada);
    cudaGetSymbolAddress((void**)&hs_,   g_hs);
    cudaGetSymbolAddress((void**)&wqkvT_,g_wqkvT);
    cudaGetSymbolAddress((void**)&woT_,  g_woT);
    cudaGetSymbolAddress((void**)&q_,    g_q);
    cudaGetSymbolAddress((void**)&k_,    g_k);
    cudaGetSymbolAddress((void**)&mu_,   g_mu);
    cudaGetSymbolAddress((void**)&rs_,   g_rs);
    cudaGetSymbolAddress((void**)&qT_,   g_qT);
    cudaGetSymbolAddress((void**)&kT_,   g_kT);
    cudaGetSymbolAddress((void**)&vs_,   g_vs);
    cudaGetSymbolAddress((void**)&sc_,   g_sc);
    cudaGetSymbolAddress((void**)&at_,   g_at);
    cudaGetSymbolAddress((void**)&aos_,  g_aos);
    cudaGetSymbolAddress((void**)&x1_,   g_x1);
    cudaGetSymbolAddress((void**)&h2s_,  g_h2s);
    cudaGetSymbolAddress((void**)&w1T_,  g_w1T);
    cudaGetSymbolAddress((void**)&w3T_,  g_w3T);
    cudaGetSymbolAddress((void**)&w2T_,  g_w2T);
    cudaGetSymbolAddress((void**)&gs_,   g_gs);
    cudaGetSymbolAddress((void**)&ebuf_, g_ebuf);
    cudaGetSymbolAddress((void**)&lg_,   g_lg);
    cudaGetSymbolAddress((void**)&pr_,   g_pr);
    cudaGetSymbolAddress((void**)&tw_,   g_tw);
    cudaGetSymbolAddress((void**)&cnt_,  g_cnt);
    cudaGetSymbolAddress((void**)&list_, g_list);
    cudaGetSymbolAddress((void**)&te_,   g_te);
    cudaGetSymbolAddress((void**)&tp_,   g_tp);

    cudaFuncSetAttribute(hgemm<0,false>, cudaFuncAttributeMaxDynamicSharedMemorySize, SMEM1);
    cudaFuncSetAttribute(hgemm<1,false>, cudaFuncAttributeMaxDynamicSharedMemorySize, SMEM1);
    cudaFuncSetAttribute(hgemm<2,false>, cudaFuncAttributeMaxDynamicSharedMemorySize, SMEM1);
    cudaFuncSetAttribute(hgemm<4,false>, cudaFuncAttributeMaxDynamicSharedMemorySize, SMEM1);
    cudaFuncSetAttribute(hgemm2, cudaFuncAttributeMaxDynamicSharedMemorySize, SMEM2);

    const float eps = 1e-5f;
    const long DD = (long)D_ * D_;
    const long DK = (long)D_ * K2D;
    const long SK = (long)S_ * K2D;

    cudaStream_t s2;
    cudaStreamCreateWithFlags(&s2, cudaStreamNonBlocking);
    cudaEvent_t evFork, evQKV, evWo, evJoin, evT, evAtt, evTopk, evAux;
    cudaEventCreateWithFlags(&evFork, cudaEventDisableTiming);
    cudaEventCreateWithFlags(&evQKV,  cudaEventDisableTiming);
    cudaEventCreateWithFlags(&evWo,   cudaEventDisableTiming);
    cudaEventCreateWithFlags(&evJoin, cudaEventDisableTiming);
    cudaEventCreateWithFlags(&evT,    cudaEventDisableTiming);
    cudaEventCreateWithFlags(&evAtt,  cudaEventDisableTiming);
    cudaEventCreateWithFlags(&evTopk, cudaEventDisableTiming);
    cudaEventCreateWithFlags(&evAux,  cudaEventDisableTiming);

    // main chain start
    ada_kernel<<<ADA6/128, 128>>>(adaln, adaw, adab, ada_);

    // fork immediately: ALL weight preps on side stream (input-only)
    cudaEventRecord(evFork, 0);
    cudaStreamWaitEvent(s2, evFork, 0);
    transQKV<<<dim3(D_/64, D_/64, 3), 256, 0, s2>>>(wq, wk, wv, wqkvT_);
    cudaEventRecord(evQKV, s2);
    transS<<<dim3(D_/64, D_/64, 1), 256, 0, s2>>>(wo, woT_, D_, D_, 0, 0);
    cudaEventRecord(evWo, s2);
    transS<<<dim3(H_/64, D_/64, E_), 256, 0, s2>>>(w1, w1T_, D_, H_, (long)D_*H_, (long)H_*K2D);
    transS<<<dim3(H_/64, D_/64, E_), 256, 0, s2>>>(w3, w3T_, D_, H_, (long)D_*H_, (long)H_*K2D);
    transS<<<dim3(D_/64, H_/64, E_), 256, 0, s2>>>(w2, w2T_, H_, D_, (long)H_*D_, (long)D_*K2H);
    cudaEventRecord(evJoin, s2);

    // main chain (ln overlaps transQKV)
    ln_kernel<<<BS_/8, 256>>>(x, nullptr, hs_, anw, anb, ada_ + D_, ada_, ADA6, eps,
        nullptr, nullptr, nullptr);
    cudaStreamWaitEvent(0, evQKV, 0);
    hgemm<4,false><<<dim3(16,24,1), 256, SMEM1>>>(hs_, 0, wqkvT_, 0, D_, 3*D_, BS_,
        nullptr, nullptr, q_, k_, 0, vs_, 1024, 0, nullptr, nullptr, 0);

    // q/k: fused stats(+cnt zero) + normalize-transpose-split
    qk_stats<<<2*BS_/8, 256>>>(q_, k_, mu_, rs_, cnt_, eps);
    transSN<<<dim3(D_/64, S_/64, 2*B_), 256>>>(q_, k_, qT_, kT_, qnw, qnb, knw, knb, mu_, rs_);

    // attention mid-chain: batches {0,1} on main, {2,3} on s2 (batch-disjoint)
    cudaEventRecord(evT, 0);
    cudaStreamWaitEvent(s2, evT, 0);
    hgemm<0,false><<<dim3(4,8,2), 256, SMEM1>>>(qT_, DK, kT_, DK,
        S_, D_, D_, nullptr, nullptr, sc_, nullptr, DD, nullptr, 0, 0, nullptr, nullptr, 0);
    softmax_kernel<<<2*D_/8, 256>>>(sc_, at_);
    hgemm<2,false><<<dim3(4,8,2), 256, SMEM1>>>(vs_, SK, at_, DK,
        D_, D_, S_, nullptr, nullptr, nullptr, nullptr, 0, aos_, D_, SK, nullptr, nullptr, 0);
    hgemm<0,false><<<dim3(4,8,2), 256, SMEM1, s2>>>(qT_ + 2*DK, DK, kT_ + 2*DK, DK,
        S_, D_, D_, nullptr, nullptr, sc_ + 2*DD, nullptr, DD, nullptr, 0, 0, nullptr, nullptr, 0);
    softmax_kernel<<<2*D_/8, 256, 0, s2>>>(sc_ + 2*DD, at_ + 2*DK);
    hgemm<2,false><<<dim3(4,8,2), 256, SMEM1, s2>>>(vs_ + 2*SK, SK, at_ + 2*DK, DK,
        D_, D_, S_, nullptr, nullptr, nullptr, nullptr, 0, aos_ + 2*SK, D_, SK, nullptr, nullptr, 0);
    cudaEventRecord(evAtt, s2);

    // join both halves + wo-prep, then x1 = x + gate_msa * (ao @ wo)
    cudaStreamWaitEvent(0, evAtt, 0);
    cudaStreamWaitEvent(0, evWo, 0);
    hgemm<1,false><<<dim3(16,8,1), 256, SMEM1>>>(aos_, 0, woT_, 0, D_, D_, BS_,
        nullptr, nullptr, x1_, nullptr, 0, nullptr, 0, 0, x, ada_ + 2L*D_, ADA6);

    // h2 = modulate(LN(x1), mlp): split out + fused router logits
    ln_kernel<<<BS_/8, 256>>>(x1_, nullptr, h2s_, fnw, fnb, ada_ + 4L*D_, ada_ + 3L*D_,
        ADA6, eps, rw, rb, lg_);

    // seq-norm + top-2 dispatch (exact fp32)
    seqnorm_kernel<<<B_*E_, 256>>>(lg_);
    topk_kernel<<<BS_/256, 256>>>(lg_, pr_, cnt_, list_, te_, tp_, tw_);

    // aux overlaps with MoE GEMMs on side stream
    cudaEventRecord(evTopk, 0);
    cudaStreamWaitEvent(s2, evTopk, 0);
    aux_kernel<<<1, 256, 0, s2>>>(pr_, out, (long)out_size);
    cudaEventRecord(evAux, s2);

    // MoE up (fused dual-B) + down
    cudaStreamWaitEvent(0, evJoin, 0);
    hgemm2<<<dim3(CAP/128, H_/128, E_), 256, SMEM2>>>(h2s_, w1T_, w3T_, (long)H_*K2D,
        D_, H_, CAP, cnt_, list_, gs_, (long)CAP*K2H);
    hgemm<0,false><<<dim3(16,8,E_), 256, SMEM1>>>(gs_, (long)CAP*K2H, w2T_, (long)D_*K2H,
        H_, D_, CAP, cnt_, nullptr, ebuf_, nullptr, (long)CAP*D_, nullptr, 0, 0, nullptr, nullptr, 0);

    // combine + join aux
    combine_kernel<<<(int)(BSD/1024), 256>>>(ebuf_, te_, tp_, tw_, out);
    cudaStreamWaitEvent(0, evAux, 0);

    cudaEventDestroy(evFork);
    cudaEventDestroy(evQKV);
    cudaEventDestroy(evWo);
    cudaEventDestroy(evJoin);
    cudaEventDestroy(evT);
    cudaEventDestroy(evAtt);
    cudaEventDestroy(evTopk);
    cudaEventDestroy(evAux);
    cudaStreamDestroy(s2);
}